// round 12
// baseline (speedup 1.0000x reference)
#include <cuda_runtime.h>
#include <cuda_bf16.h>
#include <mma.h>
#include <math.h>

using namespace nvcuda;

#define TT 512
#define BB 64
#define II 1024
#define HH 1024
#define BH (BB*HH)          // 65536
#define NBLK 128            // persistent grid, 1 block/SM
#define RTHREADS 512        // recurrence block size (16 warps)

// ---------------- device scratch ----------------
__device__ float g_xz[(size_t)TT*BH];
__device__ float g_xr[(size_t)TT*BH];
__device__ float g_xc[(size_t)TT*BH];
__device__ float g_h[BH];
__device__ float g_z[BH];
__device__ __nv_bfloat16 g_h_hi[BH];
__device__ __nv_bfloat16 g_h_lo[BH];
__device__ __nv_bfloat16 g_rh_hi[BH];
__device__ __nv_bfloat16 g_rh_lo[BH];

// bf16 split mirrors for the input projection
__device__ __nv_bfloat16 g_x_hi[(size_t)TT*BB*II];
__device__ __nv_bfloat16 g_x_lo[(size_t)TT*BB*II];
__device__ __nv_bfloat16 g_wi_hi[(size_t)3*HH*II];
__device__ __nv_bfloat16 g_wi_lo[(size_t)3*HH*II];

// grid barrier: counter zeroed each launch by reset kernel (own graph node)
__device__ unsigned g_arrive = 0;

__global__ void reset_barrier() { g_arrive = 0; }

__device__ __forceinline__ void grid_barrier_t(unsigned target) {
    __syncthreads();
    if (threadIdx.x == 0) {
        __threadfence();
        asm volatile("red.release.gpu.global.add.u32 [%0], %1;"
                     :: "l"(&g_arrive), "r"(1u) : "memory");
        unsigned v;
        do {
            asm volatile("ld.acquire.gpu.global.u32 %0, [%1];"
                         : "=r"(v) : "l"(&g_arrive) : "memory");
        } while (v < target);
    }
    __syncthreads();
}

// ---------------- cp.async helpers (projection only) ----------------
__device__ __forceinline__ void cpa16(void* s, const void* g) {
    unsigned sa = (unsigned)__cvta_generic_to_shared(s);
    asm volatile("cp.async.cg.shared.global [%0], [%1], 16;" :: "r"(sa), "l"(g));
}
__device__ __forceinline__ void cpa_commit() {
    asm volatile("cp.async.commit_group;");
}
template<int N>
__device__ __forceinline__ void cpa_wait() {
    asm volatile("cp.async.wait_group %0;" :: "n"(N));
}

// ---------------- split conversion kernels ----------------
__global__ void convert_x(const float* __restrict__ x)
{
    size_t i4 = (size_t)blockIdx.x * blockDim.x + threadIdx.x;
    size_t n4 = (size_t)TT * BB * II / 4;
    if (i4 >= n4) return;
    float4 v = *(const float4*)&x[i4 * 4];
    float f[4] = {v.x, v.y, v.z, v.w};
    union { __nv_bfloat16 h[4]; uint2 u; } HI, LO;
#pragma unroll
    for (int q = 0; q < 4; q++) {
        __nv_bfloat16 hv = __float2bfloat16(f[q]);
        HI.h[q] = hv;
        LO.h[q] = __float2bfloat16(f[q] - __bfloat162float(hv));
    }
    *(uint2*)&g_x_hi[i4 * 4] = HI.u;
    *(uint2*)&g_x_lo[i4 * 4] = LO.u;
}

__global__ void convert_w(const float* __restrict__ Wzi,
                          const float* __restrict__ Wri,
                          const float* __restrict__ Wci)
{
    const float* W = (blockIdx.y == 0) ? Wzi : (blockIdx.y == 1) ? Wri : Wci;
    size_t base = (size_t)blockIdx.y * HH * II;
    size_t i4 = (size_t)blockIdx.x * blockDim.x + threadIdx.x;
    if (i4 >= (size_t)HH * II / 4) return;
    float4 v = *(const float4*)&W[i4 * 4];
    float f[4] = {v.x, v.y, v.z, v.w};
    union { __nv_bfloat16 h[4]; uint2 u; } HI, LO;
#pragma unroll
    for (int q = 0; q < 4; q++) {
        __nv_bfloat16 hv = __float2bfloat16(f[q]);
        HI.h[q] = hv;
        LO.h[q] = __float2bfloat16(f[q] - __bfloat162float(hv));
    }
    *(uint2*)&g_wi_hi[base + i4 * 4] = HI.u;
    *(uint2*)&g_wi_lo[base + i4 * 4] = LO.u;
}

// ---------------- tensor-core input projection (validated R8) ----------------
#define PM 128
#define PN 128
#define PK 32
#define PKP 40
#define PMAT (PM*PKP)
#define PBUF (4*PMAT)
#define PBIAS_OFF (2*PBUF)
#define PNP 136
#define PSMEM_BYTES (2*PBUF*2 + 16*PNP*4)

typedef wmma::fragment<wmma::matrix_a, 16, 16, 16, __nv_bfloat16, wmma::row_major> PFragA;
typedef wmma::fragment<wmma::matrix_b, 16, 16, 16, __nv_bfloat16, wmma::col_major> PFragB;
typedef wmma::fragment<wmma::accumulator, 16, 16, 16, float> PFragC;

__global__ __launch_bounds__(256)
void gru_input_proj_tc(const float* __restrict__ bzi, const float* __restrict__ bzh,
                       const float* __restrict__ bri, const float* __restrict__ brh,
                       const float* __restrict__ bci, const float* __restrict__ bch)
{
    extern __shared__ __nv_bfloat16 ps[];
    float* bias_sm = (float*)&ps[PBIAS_OFF];

    const int gate = blockIdx.z;
    const float* b1; const float* b2; float* out;
    if (gate == 0)      { b1 = bzi; b2 = bzh; out = g_xz; }
    else if (gate == 1) { b1 = bri; b2 = brh; out = g_xr; }
    else                { b1 = bci; b2 = bch; out = g_xc; }

    const __nv_bfloat16* Wh = g_wi_hi + (size_t)gate * HH * II;
    const __nv_bfloat16* Wl = g_wi_lo + (size_t)gate * HH * II;

    const int m0 = blockIdx.y * PM;
    const int n0 = blockIdx.x * PN;
    const int tid = threadIdx.x;
    const int warp = tid >> 5;
    const int wm = warp >> 2;
    const int wn = warp & 3;

    for (int idx = tid; idx < 16 * PN; idx += 256) {
        int r = idx >> 7, c = idx & 127;
        bias_sm[r * PNP + c] = b1[n0 + c] + b2[n0 + c];
    }

    const int sr = tid >> 1;
    const int sh = tid & 1;

    auto fill = [&](int buf, int k0) {
        __nv_bfloat16* base = ps + buf * PBUF;
#pragma unroll
        for (int i = 0; i < 2; i++) {
            int kc = sh * 16 + i * 8;
            cpa16(&base[sr * PKP + kc],            &g_x_hi[(size_t)(m0 + sr) * II + k0 + kc]);
            cpa16(&base[PMAT + sr * PKP + kc],     &g_x_lo[(size_t)(m0 + sr) * II + k0 + kc]);
            cpa16(&base[2*PMAT + sr * PKP + kc],   &Wh[(size_t)(n0 + sr) * II + k0 + kc]);
            cpa16(&base[3*PMAT + sr * PKP + kc],   &Wl[(size_t)(n0 + sr) * II + k0 + kc]);
        }
        cpa_commit();
    };

    fill(0, 0);
    __syncthreads();

    PFragC c[4][2];
#pragma unroll
    for (int mf = 0; mf < 4; mf++)
#pragma unroll
        for (int nf = 0; nf < 2; nf++)
            wmma::load_matrix_sync(c[mf][nf],
                bias_sm + wn * 32 + nf * 16, PNP, wmma::mem_row_major);

    for (int kt = 0; kt < II / PK; kt++) {
        if (kt < II / PK - 1) fill((kt + 1) & 1, (kt + 1) * PK);
        if (kt < II / PK - 1) cpa_wait<1>(); else cpa_wait<0>();
        __syncthreads();
        const __nv_bfloat16* base = ps + (kt & 1) * PBUF;
        const __nv_bfloat16* Ah = base;
        const __nv_bfloat16* Al = base + PMAT;
        const __nv_bfloat16* Bh = base + 2 * PMAT;
        const __nv_bfloat16* Bl = base + 3 * PMAT;
#pragma unroll
        for (int ks = 0; ks < 2; ks++) {
            PFragA ah[4], al[4];
            PFragB bh[2], bl[2];
#pragma unroll
            for (int mf = 0; mf < 4; mf++) {
                wmma::load_matrix_sync(ah[mf], Ah + (wm * 64 + mf * 16) * PKP + ks * 16, PKP);
                wmma::load_matrix_sync(al[mf], Al + (wm * 64 + mf * 16) * PKP + ks * 16, PKP);
            }
#pragma unroll
            for (int nf = 0; nf < 2; nf++) {
                wmma::load_matrix_sync(bh[nf], Bh + (wn * 32 + nf * 16) * PKP + ks * 16, PKP);
                wmma::load_matrix_sync(bl[nf], Bl + (wn * 32 + nf * 16) * PKP + ks * 16, PKP);
            }
#pragma unroll
            for (int mf = 0; mf < 4; mf++)
#pragma unroll
                for (int nf = 0; nf < 2; nf++) {
                    wmma::mma_sync(c[mf][nf], ah[mf], bh[nf], c[mf][nf]);
                    wmma::mma_sync(c[mf][nf], ah[mf], bl[nf], c[mf][nf]);
                    wmma::mma_sync(c[mf][nf], al[mf], bh[nf], c[mf][nf]);
                }
        }
        __syncthreads();
    }

#pragma unroll
    for (int mf = 0; mf < 4; mf++)
#pragma unroll
        for (int nf = 0; nf < 2; nf++) {
            int m = m0 + wm * 64 + mf * 16;
            int n = n0 + wn * 32 + nf * 16;
            wmma::store_matrix_sync(out + (size_t)m * HH + n, c[mf][nf], HH,
                                    wmma::mem_row_major);
        }
}

// ---------------- tensor-core persistent recurrence ----------------
// 512 threads (16 warps). A-fragments loaded DIRECTLY from global (no smem
// staging, no main-loop syncs): each warp's (rows, k-slice) is private.
// Weights resident in smem. pbuf for cross-warp k-split reduction.
// Phase A: C[64x16], warp = (wm 0..3, ks 0..3).
// Phase B: C[32x16], warp = (wm 0..1, ks 0..7).
#define SM_PBUF_OFF (4*1024*16)                      // bf16 elems before pbuf
#define SMEM_BYTES  (4*1024*16*2 + 16*1024*4 /*pbuf 16KB*/)

typedef wmma::fragment<wmma::matrix_a, 16, 16, 16, __nv_bfloat16, wmma::row_major> FragA;
typedef wmma::fragment<wmma::matrix_b, 16, 16, 16, __nv_bfloat16, wmma::row_major> FragB;
typedef wmma::fragment<wmma::accumulator, 16, 16, 16, float> FragC;

__global__ __launch_bounds__(RTHREADS, 1)
void gru_recurrence(const float* __restrict__ hidden,
                    const float* __restrict__ Wzh,
                    const float* __restrict__ Wrh,
                    const float* __restrict__ Wch,
                    float* __restrict__ out)
{
    extern __shared__ char smem[];
    __nv_bfloat16* wzr_h = (__nv_bfloat16*)smem;
    __nv_bfloat16* wzr_l = wzr_h + 1024 * 16;
    __nv_bfloat16* wc_h  = wzr_l + 1024 * 16;
    __nv_bfloat16* wc_l  = wc_h  + 1024 * 16;
    float* pbuf = (float*)(wc_l + 1024 * 16);

    const int tid  = threadIdx.x;
    const int bid  = blockIdx.x;
    const int warp = tid >> 5;

    const int gate = bid >> 6;
    const int n0g  = (bid & 63) * 16;
    const int n0c  = (bid & 63) * 16;
    const int bh   = bid >> 6;

    unsigned bar_n = 0;

    // ---- one-time: weight slices -> bf16 hi/lo in smem (512 threads) ----
    {
        const float* WA = gate ? Wrh : Wzh;
        int j   = tid >> 5;          // 0..15 col
        int kc5 = tid & 31;          // k chunk of 8
#pragma unroll
        for (int i = 0; i < 4; i++) {
            int k = i * 256 + kc5 * 8;
            float4 v0 = *(const float4*)&WA[(size_t)(n0g + j) * HH + k];
            float4 v1 = *(const float4*)&WA[(size_t)(n0g + j) * HH + k + 4];
            float f[8] = {v0.x,v0.y,v0.z,v0.w,v1.x,v1.y,v1.z,v1.w};
#pragma unroll
            for (int q = 0; q < 8; q++) {
                __nv_bfloat16 hv = __float2bfloat16(f[q]);
                wzr_h[(k + q) * 16 + j] = hv;
                wzr_l[(k + q) * 16 + j] = __float2bfloat16(f[q] - __bfloat162float(hv));
            }
            float4 w0 = *(const float4*)&Wch[(size_t)(n0c + j) * HH + k];
            float4 w1 = *(const float4*)&Wch[(size_t)(n0c + j) * HH + k + 4];
            float g[8] = {w0.x,w0.y,w0.z,w0.w,w1.x,w1.y,w1.z,w1.w};
#pragma unroll
            for (int q = 0; q < 8; q++) {
                __nv_bfloat16 hv = __float2bfloat16(g[q]);
                wc_h[(k + q) * 16 + j] = hv;
                wc_l[(k + q) * 16 + j] = __float2bfloat16(g[q] - __bfloat162float(hv));
            }
        }
    }

    // ---- init hidden ----
    for (int i = bid * RTHREADS + tid; i < BH; i += NBLK * RTHREADS) {
        float v = hidden[i];
        g_h[i] = v;
        __nv_bfloat16 hv = __float2bfloat16(v);
        g_h_hi[i] = hv;
        g_h_lo[i] = __float2bfloat16(v - __bfloat162float(hv));
    }
    bar_n++; grid_barrier_t(bar_n * NBLK);

    for (int t = 0; t < TT; t++) {
        // =================== Phase A: z | r, C[64 x 16] ===================
        {
            const int wm = warp >> 2;            // m-tile 0..3
            const int ks = warp & 3;             // k quarter (32 k per 128)
            const int m0 = wm * 16;

            FragC c0, c1, c2;
            wmma::fill_fragment(c0, 0.f);
            wmma::fill_fragment(c1, 0.f);
            wmma::fill_fragment(c2, 0.f);

            const __nv_bfloat16* Ahg = g_h_hi + (size_t)m0 * HH;
            const __nv_bfloat16* Alg = g_h_lo + (size_t)m0 * HH;

#pragma unroll
            for (int kt = 0; kt < 8; kt++) {
#pragma unroll
                for (int s = 0; s < 2; s++) {
                    int k = kt * 128 + ks * 32 + s * 16;
                    FragA ah, al; FragB bhf, blf;
                    wmma::load_matrix_sync(ah, Ahg + k, HH);
                    wmma::load_matrix_sync(al, Alg + k, HH);
                    wmma::load_matrix_sync(bhf, wzr_h + k * 16, 16);
                    wmma::load_matrix_sync(blf, wzr_l + k * 16, 16);
                    wmma::mma_sync(c0, ah, bhf, c0);
                    wmma::mma_sync(c1, ah, blf, c1);
                    wmma::mma_sync(c2, al, bhf, c2);
                }
            }
#pragma unroll
            for (int i = 0; i < c0.num_elements; i++) c0.x[i] += c1.x[i] + c2.x[i];
            wmma::store_matrix_sync(pbuf + ks * 1024 + m0 * 16, c0, 16, wmma::mem_row_major);
            __syncthreads();

            // epilogue: 1024 outputs, 2 per thread
            int b  = tid >> 3;
            int cg = (tid & 7) * 2;
            float s0 = 0.f, s1 = 0.f;
#pragma unroll
            for (int q = 0; q < 4; q++) {
                s0 += pbuf[q * 1024 + b * 16 + cg + 0];
                s1 += pbuf[q * 1024 + b * 16 + cg + 1];
            }
            int col = n0g + cg;
            int idx = b * HH + col;
            if (gate == 0) {
                float2 xg = *(const float2*)&g_xz[(size_t)t * BH + idx];
                float2 r;
                r.x = 1.f / (1.f + __expf(-(s0 + xg.x)));
                r.y = 1.f / (1.f + __expf(-(s1 + xg.y)));
                *(float2*)&g_z[idx] = r;
            } else {
                float2 xg = *(const float2*)&g_xr[(size_t)t * BH + idx];
                float2 hv = *(const float2*)&g_h[idx];
                float rh0 = hv.x / (1.f + __expf(-(s0 + xg.x)));
                float rh1 = hv.y / (1.f + __expf(-(s1 + xg.y)));
                __nv_bfloat16 h0 = __float2bfloat16(rh0);
                __nv_bfloat16 h1 = __float2bfloat16(rh1);
                __nv_bfloat162 hi2, lo2;
                hi2.x = h0; hi2.y = h1;
                lo2.x = __float2bfloat16(rh0 - __bfloat162float(h0));
                lo2.y = __float2bfloat16(rh1 - __bfloat162float(h1));
                *(__nv_bfloat162*)&g_rh_hi[idx] = hi2;
                *(__nv_bfloat162*)&g_rh_lo[idx] = lo2;
            }
        }
        bar_n++; grid_barrier_t(bar_n * NBLK);

        // =================== Phase B: candidate, C[32 x 16] ===================
        {
            const int wm = warp >> 3;            // m-tile 0..1
            const int ks = warp & 7;             // k eighth (16 k per 128)
            const int m0 = wm * 16;

            FragC c0, c1, c2;
            wmma::fill_fragment(c0, 0.f);
            wmma::fill_fragment(c1, 0.f);
            wmma::fill_fragment(c2, 0.f);

            const __nv_bfloat16* Ahg = g_rh_hi + (size_t)(bh * 32 + m0) * HH;
            const __nv_bfloat16* Alg = g_rh_lo + (size_t)(bh * 32 + m0) * HH;

#pragma unroll
            for (int kt = 0; kt < 8; kt++) {
                int k = kt * 128 + ks * 16;
                FragA ah, al; FragB bhf, blf;
                wmma::load_matrix_sync(ah, Ahg + k, HH);
                wmma::load_matrix_sync(al, Alg + k, HH);
                wmma::load_matrix_sync(bhf, wc_h + k * 16, 16);
                wmma::load_matrix_sync(blf, wc_l + k * 16, 16);
                wmma::mma_sync(c0, ah, bhf, c0);
                wmma::mma_sync(c1, ah, blf, c1);
                wmma::mma_sync(c2, al, bhf, c2);
            }
#pragma unroll
            for (int i = 0; i < c0.num_elements; i++) c0.x[i] += c1.x[i] + c2.x[i];
            wmma::store_matrix_sync(pbuf + ks * 512 + m0 * 16, c0, 16, wmma::mem_row_major);
            __syncthreads();

            // epilogue: 512 outputs, 1 per thread
            int row = tid >> 4;
            int cg  = tid & 15;
            float s = 0.f;
#pragma unroll
            for (int q = 0; q < 8; q++)
                s += pbuf[q * 512 + row * 16 + cg];
            int b   = bh * 32 + row;
            int col = n0c + cg;
            size_t base = (size_t)t * BH + b * HH + col;
            int idx = b * HH + col;
            float xc = g_xc[base];
            float z  = g_z[idx];
            float h0 = g_h[idx];
            float cc = tanhf(s + xc);
            float hn = (1.f - z) * h0 + z * cc;
            g_h[idx] = hn;
            out[base] = hn;
            {
                __nv_bfloat16 hh = __float2bfloat16(hn);
                g_h_hi[idx] = hh;
                g_h_lo[idx] = __float2bfloat16(hn - __bfloat162float(hh));
            }
            if (t == TT - 1) out[(size_t)TT * BH + idx] = hn;
        }
        bar_n++; grid_barrier_t(bar_n * NBLK);
    }
}

// ---------------- launch ----------------
extern "C" void kernel_launch(void* const* d_in, const int* in_sizes, int n_in,
                              void* d_out, int out_size)
{
    const float* x      = (const float*)d_in[0];
    const float* hidden = (const float*)d_in[1];
    const float* Wzi = (const float*)d_in[2];  const float* bzi = (const float*)d_in[3];
    const float* Wzh = (const float*)d_in[4];  const float* bzh = (const float*)d_in[5];
    const float* Wri = (const float*)d_in[6];  const float* bri = (const float*)d_in[7];
    const float* Wrh = (const float*)d_in[8];  const float* brh = (const float*)d_in[9];
    const float* Wci = (const float*)d_in[10]; const float* bci = (const float*)d_in[11];
    const float* Wch = (const float*)d_in[12]; const float* bch = (const float*)d_in[13];
    float* out = (float*)d_out;

    reset_barrier<<<1, 1>>>();

    {
        size_t n4 = (size_t)TT * BB * II / 4;
        int blocks = (int)((n4 + 255) / 256);
        convert_x<<<blocks, 256>>>(x);
    }
    {
        int blocks = (HH * II / 4 + 255) / 256;
        convert_w<<<dim3(blocks, 3), 256>>>(Wzi, Wri, Wci);
    }

    cudaFuncSetAttribute(gru_input_proj_tc,
                         cudaFuncAttributeMaxDynamicSharedMemorySize, PSMEM_BYTES);
    gru_input_proj_tc<<<dim3(HH / PN, (TT * BB) / PM, 3), 256, PSMEM_BYTES>>>(
        bzi, bzh, bri, brh, bci, bch);

    cudaFuncSetAttribute(gru_recurrence,
                         cudaFuncAttributeMaxDynamicSharedMemorySize, SMEM_BYTES);
    gru_recurrence<<<NBLK, RTHREADS, SMEM_BYTES>>>(hidden, Wzh, Wrh, Wch, out);
}

// round 14
// speedup vs baseline: 1.1811x; 1.1811x over previous
#include <cuda_runtime.h>
#include <cuda_bf16.h>
#include <mma.h>
#include <math.h>

using namespace nvcuda;

#define TT 512
#define BB 64
#define II 1024
#define HH 1024
#define BH (BB*HH)          // 65536
#define NBLK 128            // persistent grid, 1 block/SM
#define RTHREADS 512        // recurrence block size (16 warps)

// ---------------- device scratch ----------------
__device__ float g_xz[(size_t)TT*BH];
__device__ float g_xr[(size_t)TT*BH];
__device__ float g_xc[(size_t)TT*BH];
__device__ float g_h[BH];
__device__ float g_z[BH];
__device__ __nv_bfloat16 g_h_hi[BH];
__device__ __nv_bfloat16 g_h_lo[BH];
__device__ __nv_bfloat16 g_rh_hi[BH];
__device__ __nv_bfloat16 g_rh_lo[BH];

// bf16 split mirrors for the input projection
__device__ __nv_bfloat16 g_x_hi[(size_t)TT*BB*II];
__device__ __nv_bfloat16 g_x_lo[(size_t)TT*BB*II];
__device__ __nv_bfloat16 g_wi_hi[(size_t)3*HH*II];
__device__ __nv_bfloat16 g_wi_lo[(size_t)3*HH*II];

// grid barrier: counter zeroed each launch by reset kernel (own graph node)
__device__ unsigned g_arrive = 0;

__global__ void reset_barrier() { g_arrive = 0; }

__device__ __forceinline__ void grid_barrier_t(unsigned target) {
    __syncthreads();
    if (threadIdx.x == 0) {
        __threadfence();
        asm volatile("red.release.gpu.global.add.u32 [%0], %1;"
                     :: "l"(&g_arrive), "r"(1u) : "memory");
        unsigned v;
        do {
            asm volatile("ld.acquire.gpu.global.u32 %0, [%1];"
                         : "=r"(v) : "l"(&g_arrive) : "memory");
        } while (v < target);
    }
    __syncthreads();
}

// ---------------- cp.async helpers (projection only) ----------------
__device__ __forceinline__ void cpa16(void* s, const void* g) {
    unsigned sa = (unsigned)__cvta_generic_to_shared(s);
    asm volatile("cp.async.cg.shared.global [%0], [%1], 16;" :: "r"(sa), "l"(g));
}
__device__ __forceinline__ void cpa_commit() {
    asm volatile("cp.async.commit_group;");
}
template<int N>
__device__ __forceinline__ void cpa_wait() {
    asm volatile("cp.async.wait_group %0;" :: "n"(N));
}

// ---------------- split conversion kernels ----------------
__global__ void convert_x(const float* __restrict__ x)
{
    size_t i4 = (size_t)blockIdx.x * blockDim.x + threadIdx.x;
    size_t n4 = (size_t)TT * BB * II / 4;
    if (i4 >= n4) return;
    float4 v = *(const float4*)&x[i4 * 4];
    float f[4] = {v.x, v.y, v.z, v.w};
    union { __nv_bfloat16 h[4]; uint2 u; } HI, LO;
#pragma unroll
    for (int q = 0; q < 4; q++) {
        __nv_bfloat16 hv = __float2bfloat16(f[q]);
        HI.h[q] = hv;
        LO.h[q] = __float2bfloat16(f[q] - __bfloat162float(hv));
    }
    *(uint2*)&g_x_hi[i4 * 4] = HI.u;
    *(uint2*)&g_x_lo[i4 * 4] = LO.u;
}

__global__ void convert_w(const float* __restrict__ Wzi,
                          const float* __restrict__ Wri,
                          const float* __restrict__ Wci)
{
    const float* W = (blockIdx.y == 0) ? Wzi : (blockIdx.y == 1) ? Wri : Wci;
    size_t base = (size_t)blockIdx.y * HH * II;
    size_t i4 = (size_t)blockIdx.x * blockDim.x + threadIdx.x;
    if (i4 >= (size_t)HH * II / 4) return;
    float4 v = *(const float4*)&W[i4 * 4];
    float f[4] = {v.x, v.y, v.z, v.w};
    union { __nv_bfloat16 h[4]; uint2 u; } HI, LO;
#pragma unroll
    for (int q = 0; q < 4; q++) {
        __nv_bfloat16 hv = __float2bfloat16(f[q]);
        HI.h[q] = hv;
        LO.h[q] = __float2bfloat16(f[q] - __bfloat162float(hv));
    }
    *(uint2*)&g_wi_hi[base + i4 * 4] = HI.u;
    *(uint2*)&g_wi_lo[base + i4 * 4] = LO.u;
}

// ---------------- tensor-core input projection (validated R8) ----------------
#define PM 128
#define PN 128
#define PK 32
#define PKP 40
#define PMAT (PM*PKP)
#define PBUF (4*PMAT)
#define PBIAS_OFF (2*PBUF)
#define PNP 136
#define PSMEM_BYTES (2*PBUF*2 + 16*PNP*4)

typedef wmma::fragment<wmma::matrix_a, 16, 16, 16, __nv_bfloat16, wmma::row_major> PFragA;
typedef wmma::fragment<wmma::matrix_b, 16, 16, 16, __nv_bfloat16, wmma::col_major> PFragB;
typedef wmma::fragment<wmma::accumulator, 16, 16, 16, float> PFragC;

__global__ __launch_bounds__(256)
void gru_input_proj_tc(const float* __restrict__ bzi, const float* __restrict__ bzh,
                       const float* __restrict__ bri, const float* __restrict__ brh,
                       const float* __restrict__ bci, const float* __restrict__ bch)
{
    extern __shared__ __nv_bfloat16 ps[];
    float* bias_sm = (float*)&ps[PBIAS_OFF];

    const int gate = blockIdx.z;
    const float* b1; const float* b2; float* out;
    if (gate == 0)      { b1 = bzi; b2 = bzh; out = g_xz; }
    else if (gate == 1) { b1 = bri; b2 = brh; out = g_xr; }
    else                { b1 = bci; b2 = bch; out = g_xc; }

    const __nv_bfloat16* Wh = g_wi_hi + (size_t)gate * HH * II;
    const __nv_bfloat16* Wl = g_wi_lo + (size_t)gate * HH * II;

    const int m0 = blockIdx.y * PM;
    const int n0 = blockIdx.x * PN;
    const int tid = threadIdx.x;
    const int warp = tid >> 5;
    const int wm = warp >> 2;
    const int wn = warp & 3;

    for (int idx = tid; idx < 16 * PN; idx += 256) {
        int r = idx >> 7, c = idx & 127;
        bias_sm[r * PNP + c] = b1[n0 + c] + b2[n0 + c];
    }

    const int sr = tid >> 1;
    const int sh = tid & 1;

    auto fill = [&](int buf, int k0) {
        __nv_bfloat16* base = ps + buf * PBUF;
#pragma unroll
        for (int i = 0; i < 2; i++) {
            int kc = sh * 16 + i * 8;
            cpa16(&base[sr * PKP + kc],            &g_x_hi[(size_t)(m0 + sr) * II + k0 + kc]);
            cpa16(&base[PMAT + sr * PKP + kc],     &g_x_lo[(size_t)(m0 + sr) * II + k0 + kc]);
            cpa16(&base[2*PMAT + sr * PKP + kc],   &Wh[(size_t)(n0 + sr) * II + k0 + kc]);
            cpa16(&base[3*PMAT + sr * PKP + kc],   &Wl[(size_t)(n0 + sr) * II + k0 + kc]);
        }
        cpa_commit();
    };

    fill(0, 0);
    __syncthreads();

    PFragC c[4][2];
#pragma unroll
    for (int mf = 0; mf < 4; mf++)
#pragma unroll
        for (int nf = 0; nf < 2; nf++)
            wmma::load_matrix_sync(c[mf][nf],
                bias_sm + wn * 32 + nf * 16, PNP, wmma::mem_row_major);

    for (int kt = 0; kt < II / PK; kt++) {
        if (kt < II / PK - 1) fill((kt + 1) & 1, (kt + 1) * PK);
        if (kt < II / PK - 1) cpa_wait<1>(); else cpa_wait<0>();
        __syncthreads();
        const __nv_bfloat16* base = ps + (kt & 1) * PBUF;
        const __nv_bfloat16* Ah = base;
        const __nv_bfloat16* Al = base + PMAT;
        const __nv_bfloat16* Bh = base + 2 * PMAT;
        const __nv_bfloat16* Bl = base + 3 * PMAT;
#pragma unroll
        for (int ks = 0; ks < 2; ks++) {
            PFragA ah[4], al[4];
            PFragB bh[2], bl[2];
#pragma unroll
            for (int mf = 0; mf < 4; mf++) {
                wmma::load_matrix_sync(ah[mf], Ah + (wm * 64 + mf * 16) * PKP + ks * 16, PKP);
                wmma::load_matrix_sync(al[mf], Al + (wm * 64 + mf * 16) * PKP + ks * 16, PKP);
            }
#pragma unroll
            for (int nf = 0; nf < 2; nf++) {
                wmma::load_matrix_sync(bh[nf], Bh + (wn * 32 + nf * 16) * PKP + ks * 16, PKP);
                wmma::load_matrix_sync(bl[nf], Bl + (wn * 32 + nf * 16) * PKP + ks * 16, PKP);
            }
#pragma unroll
            for (int mf = 0; mf < 4; mf++)
#pragma unroll
                for (int nf = 0; nf < 2; nf++) {
                    wmma::mma_sync(c[mf][nf], ah[mf], bh[nf], c[mf][nf]);
                    wmma::mma_sync(c[mf][nf], ah[mf], bl[nf], c[mf][nf]);
                    wmma::mma_sync(c[mf][nf], al[mf], bh[nf], c[mf][nf]);
                }
        }
        __syncthreads();
    }

#pragma unroll
    for (int mf = 0; mf < 4; mf++)
#pragma unroll
        for (int nf = 0; nf < 2; nf++) {
            int m = m0 + wm * 64 + mf * 16;
            int n = n0 + wn * 32 + nf * 16;
            wmma::store_matrix_sync(out + (size_t)m * HH + n, c[mf][nf], HH,
                                    wmma::mem_row_major);
        }
}

// ---------------- tensor-core persistent recurrence (R11 + epilogue prefetch) --
// 512 threads (16 warps). Register-prefetch staging (R8/R11-validated).
// Phase A: C[64x16], warp = (wm 0..3, ks 0..3): m-tile 16, k-slice 32/tile.
// Phase B: C[32x16], warp = (wm 0..1, ks 0..7): m-tile 16, k-slice 16/tile.
// Epilogue operands (xz/xr/xc, z, h) prefetched at phase start so their DRAM/L2
// latency overlaps the GEMM instead of trailing the last sync.
#define KPAD 136
#define HMAT (64*KPAD)
#define SMEM_BYTES (4*1024*16*2 + 2*2*HMAT*2)   // 200704

typedef wmma::fragment<wmma::matrix_a, 16, 16, 16, __nv_bfloat16, wmma::row_major> FragA;
typedef wmma::fragment<wmma::matrix_b, 16, 16, 16, __nv_bfloat16, wmma::row_major> FragB;
typedef wmma::fragment<wmma::accumulator, 16, 16, 16, float> FragC;

__global__ __launch_bounds__(RTHREADS, 1)
void gru_recurrence(const float* __restrict__ hidden,
                    const float* __restrict__ Wzh,
                    const float* __restrict__ Wrh,
                    const float* __restrict__ Wch,
                    float* __restrict__ out)
{
    extern __shared__ char smem[];
    __nv_bfloat16* wzr_h = (__nv_bfloat16*)smem;
    __nv_bfloat16* wzr_l = wzr_h + 1024 * 16;
    __nv_bfloat16* wc_h  = wzr_l + 1024 * 16;
    __nv_bfloat16* wc_l  = wc_h  + 1024 * 16;
    __nv_bfloat16* hb    = wc_l  + 1024 * 16;   // 2 bufs x (hi, lo) [64][KPAD]
    float* pbuf = (float*)hb;                    // aliases buffer 0 (16KB used)

    const int tid  = threadIdx.x;
    const int bid  = blockIdx.x;
    const int warp = tid >> 5;

    const int gate = bid >> 6;
    const int n0g  = (bid & 63) * 16;
    const int n0c  = (bid & 63) * 16;
    const int bh   = bid >> 6;

    unsigned bar_n = 0;

    // ---- one-time: weight slices -> bf16 hi/lo in smem (512 threads) ----
    {
        const float* WA = gate ? Wrh : Wzh;
        int j   = tid >> 5;          // 0..15 col
        int kc5 = tid & 31;          // k chunk of 8
#pragma unroll
        for (int i = 0; i < 4; i++) {
            int k = i * 256 + kc5 * 8;
            float4 v0 = *(const float4*)&WA[(size_t)(n0g + j) * HH + k];
            float4 v1 = *(const float4*)&WA[(size_t)(n0g + j) * HH + k + 4];
            float f[8] = {v0.x,v0.y,v0.z,v0.w,v1.x,v1.y,v1.z,v1.w};
#pragma unroll
            for (int q = 0; q < 8; q++) {
                __nv_bfloat16 hv = __float2bfloat16(f[q]);
                wzr_h[(k + q) * 16 + j] = hv;
                wzr_l[(k + q) * 16 + j] = __float2bfloat16(f[q] - __bfloat162float(hv));
            }
            float4 w0 = *(const float4*)&Wch[(size_t)(n0c + j) * HH + k];
            float4 w1 = *(const float4*)&Wch[(size_t)(n0c + j) * HH + k + 4];
            float g[8] = {w0.x,w0.y,w0.z,w0.w,w1.x,w1.y,w1.z,w1.w};
#pragma unroll
            for (int q = 0; q < 8; q++) {
                __nv_bfloat16 hv = __float2bfloat16(g[q]);
                wc_h[(k + q) * 16 + j] = hv;
                wc_l[(k + q) * 16 + j] = __float2bfloat16(g[q] - __bfloat162float(hv));
            }
        }
    }

    // ---- init hidden ----
    for (int i = bid * RTHREADS + tid; i < BH; i += NBLK * RTHREADS) {
        float v = hidden[i];
        g_h[i] = v;
        __nv_bfloat16 hv = __float2bfloat16(v);
        g_h_hi[i] = hv;
        g_h_lo[i] = __float2bfloat16(v - __bfloat162float(hv));
    }
    bar_n++; grid_barrier_t(bar_n * NBLK);

    // epilogue coordinates (fixed per thread)
    const int ea_b  = tid >> 3;             // phase A: batch row
    const int ea_cg = (tid & 7) * 2;        // phase A: col pair
    const int ea_idx = ea_b * HH + n0g + ea_cg;
    const int eb_row = tid >> 4;            // phase B
    const int eb_cg  = tid & 15;
    const int eb_idx = (bh * 32 + eb_row) * HH + n0c + eb_cg;

    for (int t = 0; t < TT; t++) {
        // =================== Phase A: z | r, C[64 x 16] ===================
        {
            const int wm = warp >> 2;            // m-tile 0..3
            const int ks = warp & 3;             // k quarter within tile
            const int m0 = wm * 16;

            // ---- epilogue operand prefetch (overlaps the whole GEMM) ----
            float2 e_xg = *(const float2*)&(gate ? g_xr : g_xz)[(size_t)t * BH + ea_idx];
            float2 e_h  = *(const float2*)&g_h[ea_idx];

            FragC c0, c1, c2;
            wmma::fill_fragment(c0, 0.f);
            wmma::fill_fragment(c1, 0.f);
            wmma::fill_fragment(c2, 0.f);

            uint4 pfh[2], pfl[2];
#pragma unroll
            for (int q = 0; q < 2; q++) {
                int c = tid * 2 + q;
                int row = c >> 4, kc2 = c & 15;
                size_t off = (size_t)row * HH + kc2 * 8;
                pfh[q] = *(const uint4*)&g_h_hi[off];
                pfl[q] = *(const uint4*)&g_h_lo[off];
            }
#pragma unroll
            for (int q = 0; q < 2; q++) {
                int c = tid * 2 + q;
                int row = c >> 4, kc2 = c & 15;
                *(uint4*)&hb[row * KPAD + kc2 * 8]        = pfh[q];
                *(uint4*)&hb[HMAT + row * KPAD + kc2 * 8] = pfl[q];
            }

            for (int kt = 0; kt < 8; kt++) {
                __syncthreads();
                if (kt < 7) {
#pragma unroll
                    for (int q = 0; q < 2; q++) {
                        int c = tid * 2 + q;
                        int row = c >> 4, kc2 = c & 15;
                        size_t off = (size_t)row * HH + (kt+1) * 128 + kc2 * 8;
                        pfh[q] = *(const uint4*)&g_h_hi[off];
                        pfl[q] = *(const uint4*)&g_h_lo[off];
                    }
                }
                const __nv_bfloat16* Hh = hb + (kt & 1) * 2 * HMAT;
                const __nv_bfloat16* Hl = Hh + HMAT;
#pragma unroll
                for (int s = 0; s < 2; s++) {
                    int kk = ks * 32 + s * 16;
                    int kg = kt * 128 + kk;
                    FragA ah, al; FragB bhf, blf;
                    wmma::load_matrix_sync(ah, Hh + m0 * KPAD + kk, KPAD);
                    wmma::load_matrix_sync(al, Hl + m0 * KPAD + kk, KPAD);
                    wmma::load_matrix_sync(bhf, wzr_h + kg * 16, 16);
                    wmma::load_matrix_sync(blf, wzr_l + kg * 16, 16);
                    wmma::mma_sync(c0, ah, bhf, c0);
                    wmma::mma_sync(c1, ah, blf, c1);
                    wmma::mma_sync(c2, al, bhf, c2);
                }
                if (kt < 7) {
                    __nv_bfloat16* Nh = hb + ((kt+1) & 1) * 2 * HMAT;
#pragma unroll
                    for (int q = 0; q < 2; q++) {
                        int c = tid * 2 + q;
                        int row = c >> 4, kc2 = c & 15;
                        *(uint4*)&Nh[row * KPAD + kc2 * 8]        = pfh[q];
                        *(uint4*)&Nh[HMAT + row * KPAD + kc2 * 8] = pfl[q];
                    }
                }
            }
#pragma unroll
            for (int i = 0; i < c0.num_elements; i++) c0.x[i] += c1.x[i] + c2.x[i];
            __syncthreads();   // last compute read buf1; pbuf (buf0) free
            wmma::store_matrix_sync(pbuf + ks * 1024 + m0 * 16, c0, 16, wmma::mem_row_major);
            __syncthreads();

            // epilogue: 1024 outputs, 2 per thread (operands already in regs)
            float s0 = 0.f, s1 = 0.f;
#pragma unroll
            for (int q = 0; q < 4; q++) {
                s0 += pbuf[q * 1024 + ea_b * 16 + ea_cg + 0];
                s1 += pbuf[q * 1024 + ea_b * 16 + ea_cg + 1];
            }
            if (gate == 0) {
                float2 r;
                r.x = 1.f / (1.f + __expf(-(s0 + e_xg.x)));
                r.y = 1.f / (1.f + __expf(-(s1 + e_xg.y)));
                *(float2*)&g_z[ea_idx] = r;
            } else {
                float rh0 = e_h.x / (1.f + __expf(-(s0 + e_xg.x)));
                float rh1 = e_h.y / (1.f + __expf(-(s1 + e_xg.y)));
                __nv_bfloat16 h0 = __float2bfloat16(rh0);
                __nv_bfloat16 h1 = __float2bfloat16(rh1);
                __nv_bfloat162 hi2, lo2;
                hi2.x = h0; hi2.y = h1;
                lo2.x = __float2bfloat16(rh0 - __bfloat162float(h0));
                lo2.y = __float2bfloat16(rh1 - __bfloat162float(h1));
                *(__nv_bfloat162*)&g_rh_hi[ea_idx] = hi2;
                *(__nv_bfloat162*)&g_rh_lo[ea_idx] = lo2;
            }
        }
        bar_n++; grid_barrier_t(bar_n * NBLK);

        // =================== Phase B: candidate, C[32 x 16] ===================
        {
            const int wm = warp >> 3;            // m-tile 0..1
            const int ks = warp & 7;             // k eighth within tile
            const int m0 = wm * 16;

            // ---- epilogue operand prefetch (z legal: A->B barrier passed) ----
            float e_xc = g_xc[(size_t)t * BH + eb_idx];
            float e_z  = g_z[eb_idx];
            float e_h  = g_h[eb_idx];

            FragC c0, c1, c2;
            wmma::fill_fragment(c0, 0.f);
            wmma::fill_fragment(c1, 0.f);
            wmma::fill_fragment(c2, 0.f);

            uint4 pfh, pfl;
            {
                int row = tid >> 4, kc2 = tid & 15;
                size_t off = (size_t)(bh * 32 + row) * HH + kc2 * 8;
                pfh = *(const uint4*)&g_rh_hi[off];
                pfl = *(const uint4*)&g_rh_lo[off];
            }
            {
                int row = tid >> 4, kc2 = tid & 15;
                *(uint4*)&hb[row * KPAD + kc2 * 8]        = pfh;
                *(uint4*)&hb[HMAT + row * KPAD + kc2 * 8] = pfl;
            }

            for (int kt = 0; kt < 8; kt++) {
                __syncthreads();
                if (kt < 7) {
                    int row = tid >> 4, kc2 = tid & 15;
                    size_t off = (size_t)(bh * 32 + row) * HH + (kt+1) * 128 + kc2 * 8;
                    pfh = *(const uint4*)&g_rh_hi[off];
                    pfl = *(const uint4*)&g_rh_lo[off];
                }
                const __nv_bfloat16* Hh = hb + (kt & 1) * 2 * HMAT;
                const __nv_bfloat16* Hl = Hh + HMAT;
                {
                    int kk = ks * 16;
                    int kg = kt * 128 + kk;
                    FragA ah, al; FragB bhf, blf;
                    wmma::load_matrix_sync(ah, Hh + m0 * KPAD + kk, KPAD);
                    wmma::load_matrix_sync(al, Hl + m0 * KPAD + kk, KPAD);
                    wmma::load_matrix_sync(bhf, wc_h + kg * 16, 16);
                    wmma::load_matrix_sync(blf, wc_l + kg * 16, 16);
                    wmma::mma_sync(c0, ah, bhf, c0);
                    wmma::mma_sync(c1, ah, blf, c1);
                    wmma::mma_sync(c2, al, bhf, c2);
                }
                if (kt < 7) {
                    __nv_bfloat16* Nh = hb + ((kt+1) & 1) * 2 * HMAT;
                    int row = tid >> 4, kc2 = tid & 15;
                    *(uint4*)&Nh[row * KPAD + kc2 * 8]        = pfh;
                    *(uint4*)&Nh[HMAT + row * KPAD + kc2 * 8] = pfl;
                }
            }
#pragma unroll
            for (int i = 0; i < c0.num_elements; i++) c0.x[i] += c1.x[i] + c2.x[i];
            __syncthreads();
            wmma::store_matrix_sync(pbuf + ks * 512 + m0 * 16, c0, 16, wmma::mem_row_major);
            __syncthreads();

            // epilogue: 512 outputs, 1 per thread (operands already in regs)
            float s = 0.f;
#pragma unroll
            for (int q = 0; q < 8; q++)
                s += pbuf[q * 512 + eb_row * 16 + eb_cg];
            size_t base = (size_t)t * BH + eb_idx;
            float cc = tanhf(s + e_xc);
            float hn = (1.f - e_z) * e_h + e_z * cc;
            g_h[eb_idx] = hn;
            out[base] = hn;
            {
                __nv_bfloat16 hh = __float2bfloat16(hn);
                g_h_hi[eb_idx] = hh;
                g_h_lo[eb_idx] = __float2bfloat16(hn - __bfloat162float(hh));
            }
            if (t == TT - 1) out[(size_t)TT * BH + eb_idx] = hn;
        }
        bar_n++; grid_barrier_t(bar_n * NBLK);
    }
}

// ---------------- launch ----------------
extern "C" void kernel_launch(void* const* d_in, const int* in_sizes, int n_in,
                              void* d_out, int out_size)
{
    const float* x      = (const float*)d_in[0];
    const float* hidden = (const float*)d_in[1];
    const float* Wzi = (const float*)d_in[2];  const float* bzi = (const float*)d_in[3];
    const float* Wzh = (const float*)d_in[4];  const float* bzh = (const float*)d_in[5];
    const float* Wri = (const float*)d_in[6];  const float* bri = (const float*)d_in[7];
    const float* Wrh = (const float*)d_in[8];  const float* brh = (const float*)d_in[9];
    const float* Wci = (const float*)d_in[10]; const float* bci = (const float*)d_in[11];
    const float* Wch = (const float*)d_in[12]; const float* bch = (const float*)d_in[13];
    float* out = (float*)d_out;

    reset_barrier<<<1, 1>>>();

    {
        size_t n4 = (size_t)TT * BB * II / 4;
        int blocks = (int)((n4 + 255) / 256);
        convert_x<<<blocks, 256>>>(x);
    }
    {
        int blocks = (HH * II / 4 + 255) / 256;
        convert_w<<<dim3(blocks, 3), 256>>>(Wzi, Wri, Wci);
    }

    cudaFuncSetAttribute(gru_input_proj_tc,
                         cudaFuncAttributeMaxDynamicSharedMemorySize, PSMEM_BYTES);
    gru_input_proj_tc<<<dim3(HH / PN, (TT * BB) / PM, 3), 256, PSMEM_BYTES>>>(
        bzi, bzh, bri, brh, bci, bch);

    cudaFuncSetAttribute(gru_recurrence,
                         cudaFuncAttributeMaxDynamicSharedMemorySize, SMEM_BYTES);
    gru_recurrence<<<NBLK, RTHREADS, SMEM_BYTES>>>(hidden, Wzh, Wrh, Wch, out);
}